// round 9
// baseline (speedup 1.0000x reference)
#include <cuda_runtime.h>
#include <math.h>
#include <stdint.h>

#define SEQ 512
#define BATCH 64
#define IN_DIM 512
#define HID 1024

#define NCTA 128
#define RTHREADS 256
#define KC 128
#define NCHUNK (HID / KC)

// smem partition (floats)
#define HS_STRIDE 68                 // [k][b] rows: 64 batches + pad (16B-aligned)
#define HS_SIZE   (KC * HS_STRIDE)   // 8704
#define W_OFF     (2 * HS_SIZE)      // 17408
#define W_GATE    (HID * 8)          // 8192
#define RED_OFF   (W_OFF + 3 * W_GATE)     // 41984
#define RED_STRIDE 36                // per-slot stride (floats) -> bank-spread
#define RED_SIZE  (15 * 16 * RED_STRIDE)   // 8640
#define SMEM_FLOATS (RED_OFF + RED_SIZE)   // 50624
#define SMEM_BYTES  (SMEM_FLOATS * 4)      // 202496

#define FLAG_STRIDE 32               // one flag per 128B line

// ---------------- scratch ----------------
__device__ float g_x[3][(size_t)SEQ * BATCH * HID];
__device__ float g_h[HID * BATCH];   // TRANSPOSED: [hid][batch]
__device__ float g_rh[HID * BATCH];  // TRANSPOSED: [hid][batch]
__device__ unsigned g_flags[NCTA * FLAG_STRIDE];  // zero-init; monotonic

__device__ __forceinline__ float sigmoidf_(float x) { return 1.0f / (1.0f + expf(-x)); }

// ---------------- f32x2 helpers ----------------
__device__ __forceinline__ void ffma2(unsigned long long& d, unsigned long long a, unsigned long long w) {
    asm("fma.rn.f32x2 %0, %1, %2, %0;" : "+l"(d) : "l"(a), "l"(w));
}
__device__ __forceinline__ unsigned long long addf32x2(unsigned long long a, unsigned long long b) {
    unsigned long long d;
    asm("add.rn.f32x2 %0, %1, %2;" : "=l"(d) : "l"(a), "l"(b));
    return d;
}
__device__ __forceinline__ unsigned long long dup2(float w) {
    unsigned long long d;
    unsigned u = __float_as_uint(w);
    asm("mov.b64 %0, {%1, %1};" : "=l"(d) : "r"(u));
    return d;
}
__device__ __forceinline__ void unpk(unsigned long long v, float& lo, float& hi) {
    unsigned x, y;
    asm("mov.b64 {%0, %1}, %2;" : "=r"(x), "=r"(y) : "l"(v));
    lo = __uint_as_float(x);
    hi = __uint_as_float(y);
}

// ---------------- sync helpers ----------------
__device__ __forceinline__ unsigned ld_acq(const unsigned* p) {
    unsigned v;
    asm volatile("ld.acquire.gpu.u32 %0, [%1];" : "=r"(v) : "l"(p) : "memory");
    return v;
}
__device__ __forceinline__ void gbar(unsigned target) {
    __threadfence();
    __syncthreads();
    if (threadIdx.x == 0) {
        asm volatile("st.release.gpu.u32 [%0], %1;"
                     :: "l"(&g_flags[blockIdx.x * FLAG_STRIDE]), "r"(target) : "memory");
    }
    if (threadIdx.x < NCTA) {
        const unsigned* p = &g_flags[threadIdx.x * FLAG_STRIDE];
        while ((int)(ld_acq(p) - target) < 0) { }
    }
    __syncthreads();
}

// ---------------------------------------------------------------------------
// init: h0 [b][k] -> g_h [k][b]
__global__ void init_h_kernel(const float* __restrict__ h0) {
    int i = blockIdx.x * blockDim.x + threadIdx.x;
    for (; i < BATCH * HID; i += gridDim.x * blockDim.x) {
        int b = i / HID;
        int k = i - b * HID;
        g_h[k * BATCH + b] = h0[i];
    }
}

// ---------------------------------------------------------------------------
// Precompute x-projections (FFMA2, known-good)
// ---------------------------------------------------------------------------
#define BM 128
#define BN 64
#define BK 32

__global__ void __launch_bounds__(256) x_gemm_kernel(
    const float* __restrict__ E,
    const float* __restrict__ Wz, const float* __restrict__ bz,
    const float* __restrict__ Wr, const float* __restrict__ br,
    const float* __restrict__ Wm, const float* __restrict__ bm)
{
    const int gate = blockIdx.z;
    const float* W    = (gate == 0) ? Wz : (gate == 1) ? Wr : Wm;
    const float* bias = (gate == 0) ? bz : (gate == 1) ? br : bm;
    float* OUT = g_x[gate];

    __shared__ float as[BK][BM + 4];
    __shared__ float bs[BK][BN + 4];

    const int tid   = threadIdx.x;
    const int mBase = blockIdx.y * BM;
    const int nBase = blockIdx.x * BN;
    const int tx = tid & 15;
    const int ty = tid >> 4;

    unsigned long long acc2[4][4];
#pragma unroll
    for (int i = 0; i < 4; i++)
#pragma unroll
        for (int j = 0; j < 4; j++) acc2[i][j] = 0ull;

    for (int k0 = 0; k0 < IN_DIM; k0 += BK) {
#pragma unroll
        for (int i = 0; i < 4; i++) {
            int f = tid + i * 256;
            int m = f >> 3;
            int kq = f & 7;
            float4 v = *(const float4*)&E[(size_t)(mBase + m) * IN_DIM + k0 + kq * 4];
            as[kq * 4 + 0][m] = v.x;
            as[kq * 4 + 1][m] = v.y;
            as[kq * 4 + 2][m] = v.z;
            as[kq * 4 + 3][m] = v.w;
        }
#pragma unroll
        for (int i = 0; i < 2; i++) {
            int f = tid + i * 256;
            int r = f >> 4;
            int cq = f & 15;
            float4 v = *(const float4*)&W[(size_t)(k0 + r) * HID + nBase + cq * 4];
            *(float4*)&bs[r][cq * 4] = v;
        }
        __syncthreads();

#pragma unroll 8
        for (int k = 0; k < BK; k++) {
            unsigned long long a[4];
#pragma unroll
            for (int i = 0; i < 4; i++)
                a[i] = *(const unsigned long long*)&as[k][ty * 8 + 2 * i];
            float4 bvv = *(const float4*)&bs[k][tx * 4];
            unsigned long long b0 = dup2(bvv.x), b1 = dup2(bvv.y),
                               b2 = dup2(bvv.z), b3 = dup2(bvv.w);
#pragma unroll
            for (int i = 0; i < 4; i++) {
                ffma2(acc2[i][0], a[i], b0);
                ffma2(acc2[i][1], a[i], b1);
                ffma2(acc2[i][2], a[i], b2);
                ffma2(acc2[i][3], a[i], b3);
            }
        }
        __syncthreads();
    }

    float dv[8][4];
#pragma unroll
    for (int i = 0; i < 4; i++)
#pragma unroll
        for (int j = 0; j < 4; j++)
            unpk(acc2[i][j], dv[2 * i][j], dv[2 * i + 1][j]);

    const float4 bv = *(const float4*)&bias[nBase + tx * 4];
#pragma unroll
    for (int p = 0; p < 8; p++) {
        int m = mBase + ty * 8 + p;
        float4 o;
        o.x = dv[p][0] + bv.x;
        o.y = dv[p][1] + bv.y;
        o.z = dv[p][2] + bv.z;
        o.w = dv[p][3] + bv.w;
        *(float4*)&OUT[(size_t)m * HID + nBase + tx * 4] = o;
    }
}

// ---------------------------------------------------------------------------
// Recurrence v5: 8b x 4j thread tiles, transposed g_h/g_rh (copy staging,
// no transpose), deeper split-K, distributed-flag barrier.
// ---------------------------------------------------------------------------
// straight copy: g_h/g_rh are [k][b]; hs is [k][HS_STRIDE]
__device__ __forceinline__ void stage_load(const float* __restrict__ src, int k0,
                                           int tid, float4 pv[8]) {
#pragma unroll
    for (int i = 0; i < 8; i++) {
        int f = tid + i * 256;          // 2048 float4 = 128 k * 16
        int k = f >> 4;
        int c4 = (f & 15) * 4;
        pv[i] = __ldcg((const float4*)&src[(size_t)(k0 + k) * BATCH + c4]);
    }
}
__device__ __forceinline__ void stage_store(float* __restrict__ hb,
                                            int tid, const float4 pv[8]) {
#pragma unroll
    for (int i = 0; i < 8; i++) {
        int f = tid + i * 256;
        int k = f >> 4;
        int c4 = (f & 15) * 4;
        *(float4*)&hb[k * HS_STRIDE + c4] = pv[i];
    }
}

// tile 8b x 4j; acc[bp*4+j] packs batches (2bp, 2bp+1)
template <int KN>
__device__ __forceinline__ void mm_chunk(const float* __restrict__ hb,
                                         const float* __restrict__ wb,
                                         int kbeg, int bo, int jq,
                                         unsigned long long acc[16]) {
    const float* hp = hb + kbeg * HS_STRIDE + bo;
    const float* wp = wb + kbeg * 8 + jq * 4;
#pragma unroll
    for (int i = 0; i < KN; i++) {
        ulonglong2 a01 = *(const ulonglong2*)(hp + i * HS_STRIDE);      // b0..b3
        ulonglong2 a23 = *(const ulonglong2*)(hp + i * HS_STRIDE + 4);  // b4..b7
        float4 wv = *(const float4*)(wp + i * 8);
        unsigned long long w0 = dup2(wv.x), w1 = dup2(wv.y), w2 = dup2(wv.z), w3 = dup2(wv.w);
        ffma2(acc[0],  a01.x, w0); ffma2(acc[1],  a01.x, w1);
        ffma2(acc[2],  a01.x, w2); ffma2(acc[3],  a01.x, w3);
        ffma2(acc[4],  a01.y, w0); ffma2(acc[5],  a01.y, w1);
        ffma2(acc[6],  a01.y, w2); ffma2(acc[7],  a01.y, w3);
        ffma2(acc[8],  a23.x, w0); ffma2(acc[9],  a23.x, w1);
        ffma2(acc[10], a23.x, w2); ffma2(acc[11], a23.x, w3);
        ffma2(acc[12], a23.y, w0); ffma2(acc[13], a23.y, w1);
        ffma2(acc[14], a23.y, w2); ffma2(acc[15], a23.y, w3);
    }
}

__device__ __forceinline__ void red_store(float* __restrict__ red, int group, int slot,
                                          const unsigned long long acc[16]) {
    unsigned long long* rp = (unsigned long long*)&red[(group * 16 + slot) * RED_STRIDE];
#pragma unroll
    for (int i = 0; i < 8; i++) {
        ulonglong2 v;
        v.x = acc[2 * i];
        v.y = acc[2 * i + 1];
        *(ulonglong2*)(rp + 2 * i) = v;
    }
}
__device__ __forceinline__ void red_add(const float* __restrict__ red, int group, int slot,
                                        unsigned long long acc[16]) {
    const unsigned long long* rp = (const unsigned long long*)&red[(group * 16 + slot) * RED_STRIDE];
#pragma unroll
    for (int i = 0; i < 8; i++) {
        ulonglong2 v = *(const ulonglong2*)(rp + 2 * i);
        acc[2 * i]     = addf32x2(acc[2 * i], v.x);
        acc[2 * i + 1] = addf32x2(acc[2 * i + 1], v.y);
    }
}

__global__ void __launch_bounds__(RTHREADS, 1) gru_rec_kernel(
    const float* __restrict__ Wz,
    const float* __restrict__ Wr,
    const float* __restrict__ Wm,
    float* __restrict__ out)
{
    extern __shared__ float sm[];
    float* hs0 = sm;
    float* hs1 = sm + HS_SIZE;
    float* wsm = sm + W_OFF;
    float* red = sm + RED_OFF;

    const int tid = threadIdx.x;
    const int j0  = blockIdx.x * 8;

    // output slot: 8 batch-octs x 2 j-quads
    const int slot = tid & 15;
    const int bo   = (slot & 7) * 8;     // batch base (8 consecutive)
    const int jq   = slot >> 3;          // 0..1
    const int jcol = j0 + jq * 4;
    // phase A: warps 0-3 gate z, 4-7 gate r; split-K 8 per gate
    const int gA  = tid >> 7;
    const int ksA = (tid & 127) >> 4;    // 0..7
    // phase B: split-K 16
    const int ksB = tid >> 4;            // 0..15

    // ---- preload persistent weight slices (once); layout [gate][k][8] ----
    for (int f = tid; f < 6144; f += RTHREADS) {
        int g = f >> 11;
        int r = f & 2047;
        int k = r >> 1;
        int jh = r & 1;
        const float* W = (g == 0) ? Wz : ((g == 1) ? Wr : Wm);
        float4 v = *(const float4*)&W[(size_t)(IN_DIM + k) * HID + j0 + jh * 4];
        *(float4*)&wsm[g * W_GATE + k * 8 + jh * 4] = v;
    }
    unsigned mygen = ld_acq(&g_flags[blockIdx.x * FLAG_STRIDE]);
    __syncthreads();

    float zreg[8][4];
#pragma unroll
    for (int i = 0; i < 8; i++)
#pragma unroll
        for (int j = 0; j < 4; j++) zreg[i][j] = 0.f;

    for (int t = 0; t < SEQ; t++) {
        // ================= Phase A: z and r =================
        unsigned long long acc[16];
#pragma unroll
        for (int i = 0; i < 16; i++) acc[i] = 0ull;

        float4 xpre[8];
        float hvv[4][8];                 // [j-lane][b] (r-owner only)
        if (ksA == 0) {
#pragma unroll
            for (int bb = 0; bb < 8; bb++)
                xpre[bb] = __ldcg((const float4*)&g_x[gA][((size_t)t * BATCH + bo + bb) * HID + jcol]);
            if (gA == 1) {
#pragma unroll
                for (int l = 0; l < 4; l++) {
                    float4 p = __ldcg((const float4*)&g_h[(jcol + l) * BATCH + bo]);
                    float4 q = __ldcg((const float4*)&g_h[(jcol + l) * BATCH + bo + 4]);
                    hvv[l][0] = p.x; hvv[l][1] = p.y; hvv[l][2] = p.z; hvv[l][3] = p.w;
                    hvv[l][4] = q.x; hvv[l][5] = q.y; hvv[l][6] = q.z; hvv[l][7] = q.w;
                }
            }
        }

        const float* wbA = wsm + gA * W_GATE;
        float4 pv[8];
        stage_load(g_h, 0, tid, pv);
        stage_store(hs0, tid, pv);
        __syncthreads();

#pragma unroll 1
        for (int c = 0; c < NCHUNK; c++) {
            float* cur = (c & 1) ? hs1 : hs0;
            float* nxt = (c & 1) ? hs0 : hs1;
            if (c < NCHUNK - 1) stage_load(g_h, (c + 1) * KC, tid, pv);
            mm_chunk<16>(cur, wbA + c * KC * 8, ksA * 16, bo, jq, acc);
            if (c < NCHUNK - 1) stage_store(nxt, tid, pv);
            __syncthreads();
        }

        if (ksA > 0) red_store(red, gA * 7 + (ksA - 1), slot, acc);
        __syncthreads();
        if (ksA == 0) {
#pragma unroll
            for (int r2 = 0; r2 < 7; r2++) red_add(red, gA * 7 + r2, slot, acc);
            float dv[8][4];
#pragma unroll
            for (int bp = 0; bp < 4; bp++)
#pragma unroll
                for (int j = 0; j < 4; j++)
                    unpk(acc[bp * 4 + j], dv[2 * bp][j], dv[2 * bp + 1][j]);

            if (gA == 0) {
#pragma unroll
                for (int bb = 0; bb < 8; bb++) {
                    zreg[bb][0] = sigmoidf_(xpre[bb].x + dv[bb][0]);
                    zreg[bb][1] = sigmoidf_(xpre[bb].y + dv[bb][1]);
                    zreg[bb][2] = sigmoidf_(xpre[bb].z + dv[bb][2]);
                    zreg[bb][3] = sigmoidf_(xpre[bb].w + dv[bb][3]);
                }
            } else {
                float rr[8][4];
#pragma unroll
                for (int bb = 0; bb < 8; bb++) {
                    rr[bb][0] = sigmoidf_(xpre[bb].x + dv[bb][0]);
                    rr[bb][1] = sigmoidf_(xpre[bb].y + dv[bb][1]);
                    rr[bb][2] = sigmoidf_(xpre[bb].z + dv[bb][2]);
                    rr[bb][3] = sigmoidf_(xpre[bb].w + dv[bb][3]);
                }
#pragma unroll
                for (int l = 0; l < 4; l++) {
                    float4 a, b;
                    a.x = rr[0][l] * hvv[l][0]; a.y = rr[1][l] * hvv[l][1];
                    a.z = rr[2][l] * hvv[l][2]; a.w = rr[3][l] * hvv[l][3];
                    b.x = rr[4][l] * hvv[l][4]; b.y = rr[5][l] * hvv[l][5];
                    b.z = rr[6][l] * hvv[l][6]; b.w = rr[7][l] * hvv[l][7];
                    __stcg((float4*)&g_rh[(jcol + l) * BATCH + bo], a);
                    __stcg((float4*)&g_rh[(jcol + l) * BATCH + bo + 4], b);
                }
            }
        }
        mygen++;
        gbar(mygen);   // rh globally visible

        // ================= Phase B: m gate =================
#pragma unroll
        for (int i = 0; i < 16; i++) acc[i] = 0ull;

        float4 xmpre[8];
        float hbv[4][8];
        if (ksB == 0) {
#pragma unroll
            for (int bb = 0; bb < 8; bb++)
                xmpre[bb] = __ldcg((const float4*)&g_x[2][((size_t)t * BATCH + bo + bb) * HID + jcol]);
#pragma unroll
            for (int l = 0; l < 4; l++) {
                float4 p = __ldcg((const float4*)&g_h[(jcol + l) * BATCH + bo]);
                float4 q = __ldcg((const float4*)&g_h[(jcol + l) * BATCH + bo + 4]);
                hbv[l][0] = p.x; hbv[l][1] = p.y; hbv[l][2] = p.z; hbv[l][3] = p.w;
                hbv[l][4] = q.x; hbv[l][5] = q.y; hbv[l][6] = q.z; hbv[l][7] = q.w;
            }
        }

        const float* wbB = wsm + 2 * W_GATE;
        stage_load(g_rh, 0, tid, pv);
        stage_store(hs0, tid, pv);
        __syncthreads();

#pragma unroll 1
        for (int c = 0; c < NCHUNK; c++) {
            float* cur = (c & 1) ? hs1 : hs0;
            float* nxt = (c & 1) ? hs0 : hs1;
            if (c < NCHUNK - 1) stage_load(g_rh, (c + 1) * KC, tid, pv);
            mm_chunk<8>(cur, wbB + c * KC * 8, ksB * 8, bo, jq, acc);
            if (c < NCHUNK - 1) stage_store(nxt, tid, pv);
            __syncthreads();
        }

        if (ksB > 0) red_store(red, ksB - 1, slot, acc);
        __syncthreads();
        if (ksB == 0) {
#pragma unroll
            for (int r2 = 0; r2 < 15; r2++) red_add(red, r2, slot, acc);
            float dv[8][4];
#pragma unroll
            for (int bp = 0; bp < 4; bp++)
#pragma unroll
                for (int j = 0; j < 4; j++)
                    unpk(acc[bp * 4 + j], dv[2 * bp][j], dv[2 * bp + 1][j]);

            float hn[8][4];
#pragma unroll
            for (int bb = 0; bb < 8; bb++) {
                float xm[4] = {xmpre[bb].x, xmpre[bb].y, xmpre[bb].z, xmpre[bb].w};
#pragma unroll
                for (int l = 0; l < 4; l++) {
                    float ht = tanhf(xm[l] + dv[bb][l]);
                    float hv = hbv[l][bb];
                    hn[bb][l] = hv + zreg[bb][l] * (ht - hv);
                }
            }
            // out: [b][t][hid]
#pragma unroll
            for (int bb = 0; bb < 8; bb++) {
                float4 o = make_float4(hn[bb][0], hn[bb][1], hn[bb][2], hn[bb][3]);
                __stcg((float4*)&out[((size_t)(bo + bb) * SEQ + t) * HID + jcol], o);
            }
            // g_h transposed: [hid][batch]
#pragma unroll
            for (int l = 0; l < 4; l++) {
                float4 a = make_float4(hn[0][l], hn[1][l], hn[2][l], hn[3][l]);
                float4 b = make_float4(hn[4][l], hn[5][l], hn[6][l], hn[7][l]);
                __stcg((float4*)&g_h[(jcol + l) * BATCH + bo], a);
                __stcg((float4*)&g_h[(jcol + l) * BATCH + bo + 4], b);
            }
        }
        mygen++;
        gbar(mygen);   // h_new globally visible
    }
}

// ---------------------------------------------------------------------------
extern "C" void kernel_launch(void* const* d_in, const int* in_sizes, int n_in,
                              void* d_out, int out_size)
{
    const float* E  = (const float*)d_in[0];
    const float* h0 = (const float*)d_in[1];
    const float* Wz = (const float*)d_in[2];
    const float* bz = (const float*)d_in[3];
    const float* Wr = (const float*)d_in[4];
    const float* br = (const float*)d_in[5];
    const float* Wm = (const float*)d_in[6];
    const float* bm = (const float*)d_in[7];
    float* out = (float*)d_out;

    static int attr_done = 0;
    if (!attr_done) {
        cudaFuncSetAttribute(gru_rec_kernel,
                             cudaFuncAttributeMaxDynamicSharedMemorySize, SMEM_BYTES);
        attr_done = 1;
    }

    init_h_kernel<<<64, 256>>>(h0);

    dim3 gg(HID / BN, (SEQ * BATCH) / BM, 3);
    x_gemm_kernel<<<gg, 256>>>(E, Wz, bz, Wr, br, Wm, bm);

    gru_rec_kernel<<<NCTA, RTHREADS, SMEM_BYTES>>>(Wz, Wr, Wm, out);
}